// round 3
// baseline (speedup 1.0000x reference)
#include <cuda_runtime.h>
#include <cuda_bf16.h>

#define N_NODES 50000
#define N_EDGES 800000
#define D 128

// Scratch (static __device__ per allocation rules)
__device__ float g_H[N_NODES * D];        // h = x @ W   (25.6 MB)
__device__ int   g_count[N_NODES];
__device__ int   g_start[N_NODES + 1];
__device__ int   g_cursor[N_NODES];
__device__ int   g_perm[N_EDGES];

// ---------------------------------------------------------------------------
// GEMM: H[N_NODES, 128] = X[N_NODES, 128] @ W[128, 128]
// ---------------------------------------------------------------------------
#define BM 64
#define BK 16

__global__ void gemm_kernel(const float* __restrict__ X,
                            const float* __restrict__ W) {
    __shared__ float sX[BM][BK];
    __shared__ float sW[BK][D];

    const int block_m = blockIdx.x * BM;
    const int tid = threadIdx.x;           // 0..255
    const int tn = tid & 31;               // col group: cols tn*4 .. tn*4+3
    const int tm = tid >> 5;               // row group: rows tm*8 .. tm*8+7

    float acc[8][4];
#pragma unroll
    for (int i = 0; i < 8; i++)
#pragma unroll
        for (int j = 0; j < 4; j++) acc[i][j] = 0.f;

    for (int k0 = 0; k0 < D; k0 += BK) {
        {
            int r = tid >> 2;
            int c = (tid & 3) * 4;
            int gm = block_m + r;
            float4 xv = make_float4(0.f, 0.f, 0.f, 0.f);
            if (gm < N_NODES)
                xv = *(const float4*)&X[gm * D + k0 + c];
            *(float4*)&sX[r][c] = xv;
        }
        {
            const float4* Wv = (const float4*)&W[k0 * D];
            float4* sWv = (float4*)&sW[0][0];
            sWv[tid]       = Wv[tid];
            sWv[tid + 256] = Wv[tid + 256];
        }
        __syncthreads();

#pragma unroll
        for (int k = 0; k < BK; k++) {
            float b[4];
#pragma unroll
            for (int j = 0; j < 4; j++) b[j] = sW[k][tn * 4 + j];
#pragma unroll
            for (int i = 0; i < 8; i++) {
                float a = sX[tm * 8 + i][k];
#pragma unroll
                for (int j = 0; j < 4; j++) acc[i][j] += a * b[j];
            }
        }
        __syncthreads();
    }

#pragma unroll
    for (int i = 0; i < 8; i++) {
        int gm = block_m + tm * 8 + i;
        if (gm < N_NODES) {
            *(float4*)&g_H[gm * D + tn * 4] =
                make_float4(acc[i][0], acc[i][1], acc[i][2], acc[i][3]);
        }
    }
}

// ---------------------------------------------------------------------------
// CSR build step 1: zero the per-row counters
// ---------------------------------------------------------------------------
__global__ void zero_count_kernel() {
    int i = blockIdx.x * blockDim.x + threadIdx.x;
    if (i < N_NODES) g_count[i] = 0;
}

// ---------------------------------------------------------------------------
// CSR build step 2: histogram of row indices
// ---------------------------------------------------------------------------
__global__ void hist_kernel(const int* __restrict__ row) {
    int e = blockIdx.x * blockDim.x + threadIdx.x;
    if (e < N_EDGES) atomicAdd(&g_count[row[e]], 1);
}

// ---------------------------------------------------------------------------
// CSR build step 3: exclusive prefix scan (single block, chunked)
// 1024 threads, each owns a contiguous chunk of ~49 counters.
// ---------------------------------------------------------------------------
__global__ void scan_kernel() {
    __shared__ int ssum[1024];
    const int tid = threadIdx.x;
    const int CHUNK = (N_NODES + 1023) / 1024;   // 49
    int begin = tid * CHUNK;
    int end = begin + CHUNK;
    if (end > N_NODES) end = N_NODES;
    if (begin > N_NODES) begin = N_NODES;

    int s = 0;
    for (int i = begin; i < end; i++) s += g_count[i];
    ssum[tid] = s;
    __syncthreads();

    // inclusive Hillis-Steele scan over the 1024 chunk sums
    for (int off = 1; off < 1024; off <<= 1) {
        int t = (tid >= off) ? ssum[tid - off] : 0;
        __syncthreads();
        ssum[tid] += t;
        __syncthreads();
    }

    int run = ssum[tid] - s;   // exclusive prefix for this chunk
    for (int i = begin; i < end; i++) {
        int c = g_count[i];
        g_start[i] = run;
        g_cursor[i] = run;
        run += c;
    }
    if (tid == 1023) g_start[N_NODES] = N_EDGES;
}

// ---------------------------------------------------------------------------
// CSR build step 4: bucket placement (edge permutation sorted by row)
// ---------------------------------------------------------------------------
__global__ void permute_kernel(const int* __restrict__ row) {
    int e = blockIdx.x * blockDim.x + threadIdx.x;
    if (e >= N_EDGES) return;
    int pos = atomicAdd(&g_cursor[row[e]], 1);
    g_perm[pos] = e;
}

// ---------------------------------------------------------------------------
// Fused CSR SpMM + bias + ReLU: one warp per output row, register accum.
// Each lane owns 4 consecutive floats of the 128-wide row.
// ---------------------------------------------------------------------------
__global__ void spmm_kernel(const float* __restrict__ vals,
                            const int* __restrict__ col,
                            const float* __restrict__ bias,
                            float* __restrict__ out) {
    int warp = (blockIdx.x * blockDim.x + threadIdx.x) >> 5;
    if (warp >= N_NODES) return;
    int lane = threadIdx.x & 31;

    int p   = g_start[warp];
    int end = g_start[warp + 1];

    float4 b = *(const float4*)&bias[lane * 4];
    float4 acc0 = b;
    float4 acc1 = make_float4(0.f, 0.f, 0.f, 0.f);

    // two-way software pipeline for MLP
    for (; p + 1 < end; p += 2) {
        int e0 = g_perm[p];
        int e1 = g_perm[p + 1];
        float v0 = __ldg(&vals[e0]);
        float v1 = __ldg(&vals[e1]);
        int c0 = __ldg(&col[e0]);
        int c1 = __ldg(&col[e1]);
        float4 h0 = *(const float4*)&g_H[(size_t)c0 * D + lane * 4];
        float4 h1 = *(const float4*)&g_H[(size_t)c1 * D + lane * 4];
        acc0.x += v0 * h0.x; acc0.y += v0 * h0.y;
        acc0.z += v0 * h0.z; acc0.w += v0 * h0.w;
        acc1.x += v1 * h1.x; acc1.y += v1 * h1.y;
        acc1.z += v1 * h1.z; acc1.w += v1 * h1.w;
    }
    if (p < end) {
        int e0 = g_perm[p];
        float v0 = __ldg(&vals[e0]);
        int c0 = __ldg(&col[e0]);
        float4 h0 = *(const float4*)&g_H[(size_t)c0 * D + lane * 4];
        acc0.x += v0 * h0.x; acc0.y += v0 * h0.y;
        acc0.z += v0 * h0.z; acc0.w += v0 * h0.w;
    }

    float4 r;
    r.x = fmaxf(acc0.x + acc1.x, 0.f);
    r.y = fmaxf(acc0.y + acc1.y, 0.f);
    r.z = fmaxf(acc0.z + acc1.z, 0.f);
    r.w = fmaxf(acc0.w + acc1.w, 0.f);
    *(float4*)&out[(size_t)warp * D + lane * 4] = r;
}

// ---------------------------------------------------------------------------
// Launch
// ---------------------------------------------------------------------------
extern "C" void kernel_launch(void* const* d_in, const int* in_sizes, int n_in,
                              void* d_out, int out_size) {
    const float* x      = (const float*)d_in[0];   // [50000,128]
    const float* weight = (const float*)d_in[1];   // [128,128]
    const float* bias   = (const float*)d_in[2];   // [128]
    const float* vals   = (const float*)d_in[3];   // [800000]
    const int*   row    = (const int*)d_in[4];     // [800000]
    const int*   col    = (const int*)d_in[5];     // [800000]
    float* out = (float*)d_out;                    // [50000,128]

    // 1) H = X @ W
    gemm_kernel<<<(N_NODES + BM - 1) / BM, 256>>>(x, weight);

    // 2) CSR build (independent of H — overlaps in issue order)
    zero_count_kernel<<<(N_NODES + 255) / 256, 256>>>();
    hist_kernel<<<(N_EDGES + 255) / 256, 256>>>(row);
    scan_kernel<<<1, 1024>>>();
    permute_kernel<<<(N_EDGES + 255) / 256, 256>>>(row);

    // 3) fused SpMM + bias + ReLU (warp per row)
    int threads = 256;                              // 8 warps/block
    int blocks = (N_NODES + 7) / 8;                 // 6250
    spmm_kernel<<<blocks, threads>>>(vals, col, bias, out);
}

// round 4
// speedup vs baseline: 1.6338x; 1.6338x over previous
#include <cuda_runtime.h>
#include <cuda_bf16.h>

#define N_NODES 50000
#define N_EDGES 800000
#define D 128

#define SCAN_B 512
#define SCAN_BLOCKS ((N_NODES + SCAN_B - 1) / SCAN_B)   // 98

// Scratch (static __device__ per allocation rules)
__device__ float g_H[N_NODES * D];        // h = x @ W   (25.6 MB)
__device__ int   g_count[N_NODES];
__device__ int   g_start[N_NODES + 1];
__device__ int   g_cursor[N_NODES];
__device__ int   g_bsum[SCAN_BLOCKS];
__device__ int   g_boff[SCAN_BLOCKS];
__device__ float g_sval[N_EDGES];         // vals sorted by row
__device__ int   g_scol[N_EDGES];         // cols sorted by row

// ---------------------------------------------------------------------------
// GEMM: H[N_NODES, 128] = X[N_NODES, 128] @ W[128, 128]
// ---------------------------------------------------------------------------
#define BM 64
#define BK 16

__global__ void gemm_kernel(const float* __restrict__ X,
                            const float* __restrict__ W) {
    __shared__ float sX[BM][BK];
    __shared__ float sW[BK][D];

    const int block_m = blockIdx.x * BM;
    const int tid = threadIdx.x;           // 0..255
    const int tn = tid & 31;
    const int tm = tid >> 5;

    float acc[8][4];
#pragma unroll
    for (int i = 0; i < 8; i++)
#pragma unroll
        for (int j = 0; j < 4; j++) acc[i][j] = 0.f;

    for (int k0 = 0; k0 < D; k0 += BK) {
        {
            int r = tid >> 2;
            int c = (tid & 3) * 4;
            int gm = block_m + r;
            float4 xv = make_float4(0.f, 0.f, 0.f, 0.f);
            if (gm < N_NODES)
                xv = *(const float4*)&X[gm * D + k0 + c];
            *(float4*)&sX[r][c] = xv;
        }
        {
            const float4* Wv = (const float4*)&W[k0 * D];
            float4* sWv = (float4*)&sW[0][0];
            sWv[tid]       = Wv[tid];
            sWv[tid + 256] = Wv[tid + 256];
        }
        __syncthreads();

#pragma unroll
        for (int k = 0; k < BK; k++) {
            float b[4];
#pragma unroll
            for (int j = 0; j < 4; j++) b[j] = sW[k][tn * 4 + j];
#pragma unroll
            for (int i = 0; i < 8; i++) {
                float a = sX[tm * 8 + i][k];
#pragma unroll
                for (int j = 0; j < 4; j++) acc[i][j] += a * b[j];
            }
        }
        __syncthreads();
    }

#pragma unroll
    for (int i = 0; i < 8; i++) {
        int gm = block_m + tm * 8 + i;
        if (gm < N_NODES) {
            *(float4*)&g_H[gm * D + tn * 4] =
                make_float4(acc[i][0], acc[i][1], acc[i][2], acc[i][3]);
        }
    }
}

// ---------------------------------------------------------------------------
// CSR build
// ---------------------------------------------------------------------------
__global__ void zero_count_kernel() {
    int i = blockIdx.x * blockDim.x + threadIdx.x;
    if (i < N_NODES) g_count[i] = 0;
}

__global__ void hist_kernel(const int* __restrict__ row) {
    int e = blockIdx.x * blockDim.x + threadIdx.x;
    if (e < N_EDGES) atomicAdd(&g_count[row[e]], 1);
}

// Level 1: per-block sum of 512 counters
__global__ void scan_reduce_kernel() {
    __shared__ int s[SCAN_B];
    int tid = threadIdx.x;
    int i = blockIdx.x * SCAN_B + tid;
    s[tid] = (i < N_NODES) ? g_count[i] : 0;
    __syncthreads();
#pragma unroll
    for (int off = SCAN_B / 2; off > 0; off >>= 1) {
        if (tid < off) s[tid] += s[tid + off];
        __syncthreads();
    }
    if (tid == 0) g_bsum[blockIdx.x] = s[0];
}

// Level 2: exclusive scan of the 98 block sums (single small block)
__global__ void scan_top_kernel() {
    __shared__ int s[128];
    int tid = threadIdx.x;                       // 0..127
    s[tid] = (tid < SCAN_BLOCKS) ? g_bsum[tid] : 0;
    __syncthreads();
    // inclusive Hillis-Steele over 128
#pragma unroll
    for (int off = 1; off < 128; off <<= 1) {
        int t = (tid >= off) ? s[tid - off] : 0;
        __syncthreads();
        s[tid] += t;
        __syncthreads();
    }
    if (tid < SCAN_BLOCKS)
        g_boff[tid] = s[tid] - g_bsum[tid];      // exclusive
    if (tid == 0) g_start[N_NODES] = N_EDGES;
}

// Level 3: intra-block exclusive scan + block offset -> g_start / g_cursor
__global__ void scan_apply_kernel() {
    __shared__ int s[SCAN_B];
    int tid = threadIdx.x;
    int i = blockIdx.x * SCAN_B + tid;
    int c = (i < N_NODES) ? g_count[i] : 0;
    s[tid] = c;
    __syncthreads();
#pragma unroll
    for (int off = 1; off < SCAN_B; off <<= 1) {
        int t = (tid >= off) ? s[tid - off] : 0;
        __syncthreads();
        s[tid] += t;
        __syncthreads();
    }
    if (i < N_NODES) {
        int ex = g_boff[blockIdx.x] + s[tid] - c;   // exclusive prefix
        g_start[i] = ex;
        g_cursor[i] = ex;
    }
}

// Bucket placement: write sorted (val, col) pairs directly
__global__ void permute_kernel(const int* __restrict__ row,
                               const int* __restrict__ col,
                               const float* __restrict__ vals) {
    int e = blockIdx.x * blockDim.x + threadIdx.x;
    if (e >= N_EDGES) return;
    int pos = atomicAdd(&g_cursor[row[e]], 1);
    g_sval[pos] = vals[e];
    g_scol[pos] = col[e];
}

// ---------------------------------------------------------------------------
// Fused CSR SpMM + bias + ReLU: one warp per output row, register accum.
// ---------------------------------------------------------------------------
__global__ void spmm_kernel(const float* __restrict__ bias,
                            float* __restrict__ out) {
    int warp = (blockIdx.x * blockDim.x + threadIdx.x) >> 5;
    if (warp >= N_NODES) return;
    int lane = threadIdx.x & 31;

    int p   = g_start[warp];
    int end = g_start[warp + 1];

    float4 b = *(const float4*)&bias[lane * 4];
    float4 acc0 = b;
    float4 acc1 = make_float4(0.f, 0.f, 0.f, 0.f);

    for (; p + 1 < end; p += 2) {
        float v0 = g_sval[p];
        float v1 = g_sval[p + 1];
        int c0 = g_scol[p];
        int c1 = g_scol[p + 1];
        float4 h0 = *(const float4*)&g_H[(size_t)c0 * D + lane * 4];
        float4 h1 = *(const float4*)&g_H[(size_t)c1 * D + lane * 4];
        acc0.x += v0 * h0.x; acc0.y += v0 * h0.y;
        acc0.z += v0 * h0.z; acc0.w += v0 * h0.w;
        acc1.x += v1 * h1.x; acc1.y += v1 * h1.y;
        acc1.z += v1 * h1.z; acc1.w += v1 * h1.w;
    }
    if (p < end) {
        float v0 = g_sval[p];
        int c0 = g_scol[p];
        float4 h0 = *(const float4*)&g_H[(size_t)c0 * D + lane * 4];
        acc0.x += v0 * h0.x; acc0.y += v0 * h0.y;
        acc0.z += v0 * h0.z; acc0.w += v0 * h0.w;
    }

    float4 r;
    r.x = fmaxf(acc0.x + acc1.x, 0.f);
    r.y = fmaxf(acc0.y + acc1.y, 0.f);
    r.z = fmaxf(acc0.z + acc1.z, 0.f);
    r.w = fmaxf(acc0.w + acc1.w, 0.f);
    *(float4*)&out[(size_t)warp * D + lane * 4] = r;
}

// ---------------------------------------------------------------------------
// Launch
// ---------------------------------------------------------------------------
extern "C" void kernel_launch(void* const* d_in, const int* in_sizes, int n_in,
                              void* d_out, int out_size) {
    const float* x      = (const float*)d_in[0];   // [50000,128]
    const float* weight = (const float*)d_in[1];   // [128,128]
    const float* bias   = (const float*)d_in[2];   // [128]
    const float* vals   = (const float*)d_in[3];   // [800000]
    const int*   row    = (const int*)d_in[4];     // [800000]
    const int*   col    = (const int*)d_in[5];     // [800000]
    float* out = (float*)d_out;                    // [50000,128]

    // 1) H = X @ W
    gemm_kernel<<<(N_NODES + BM - 1) / BM, 256>>>(x, weight);

    // 2) CSR build (fully parallel 3-level scan)
    zero_count_kernel<<<(N_NODES + 255) / 256, 256>>>();
    hist_kernel<<<(N_EDGES + 255) / 256, 256>>>(row);
    scan_reduce_kernel<<<SCAN_BLOCKS, SCAN_B>>>();
    scan_top_kernel<<<1, 128>>>();
    scan_apply_kernel<<<SCAN_BLOCKS, SCAN_B>>>();
    permute_kernel<<<(N_EDGES + 255) / 256, 256>>>(row, col, vals);

    // 3) fused SpMM + bias + ReLU (warp per row)
    spmm_kernel<<<(N_NODES + 7) / 8, 256>>>(bias, out);
}

// round 5
// speedup vs baseline: 1.6576x; 1.0146x over previous
#include <cuda_runtime.h>
#include <cuda_bf16.h>

#define N_NODES 50000
#define N_EDGES 800000
#define D 128

#define SCAN_B 512
#define SCAN_BLOCKS ((N_NODES + SCAN_B - 1) / SCAN_B)   // 98

// Scratch (static __device__ per allocation rules)
__device__ float g_H[N_NODES * D];        // h = x @ W   (25.6 MB)
__device__ int   g_count[N_NODES];
__device__ int   g_start[N_NODES + 1];
__device__ int   g_cursor[N_NODES];
__device__ int   g_bsum[SCAN_BLOCKS];
__device__ int   g_boff[SCAN_BLOCKS];
__device__ int2  g_edge[N_EDGES];         // {val_bits, col} sorted by row

// ---------------------------------------------------------------------------
// GEMM: H = X @ W.  128x128 block tile, 8x8 micro-tile per thread, BK=8.
// ---------------------------------------------------------------------------
#define GBM 128
#define GBK 8
#define SA_PAD 4   // pad A rows to 132 floats: conflict-free transpose STS

__global__ void gemm_kernel(const float* __restrict__ X,
                            const float* __restrict__ W) {
    __shared__ float sA[GBK][GBM + SA_PAD];   // X^T tile: sA[k][m]
    __shared__ float sB[GBK][D];              // W tile:   sB[k][n]

    const int tid = threadIdx.x;      // 0..255
    const int tx = tid & 15;          // n: cols tx*8 .. tx*8+7
    const int ty = tid >> 4;          // m: rows ty*8 .. ty*8+7
    const int block_m = blockIdx.x * GBM;

    // A load mapping: 128x8 tile, thread loads one float4 along k
    const int lr = tid >> 1;          // row within tile 0..127
    const int lc = (tid & 1) * 4;     // k offset 0 or 4
    // B load mapping: 8x128 tile, thread loads one float4 along n
    const int wr = tid >> 5;          // k row 0..7
    const int wc = (tid & 31) * 4;    // n col

    float acc[8][8];
#pragma unroll
    for (int i = 0; i < 8; i++)
#pragma unroll
        for (int j = 0; j < 8; j++) acc[i][j] = 0.f;

    for (int k0 = 0; k0 < D; k0 += GBK) {
        int gm = block_m + lr;
        float4 xv = make_float4(0.f, 0.f, 0.f, 0.f);
        if (gm < N_NODES) xv = *(const float4*)&X[gm * D + k0 + lc];
        sA[lc + 0][lr] = xv.x;
        sA[lc + 1][lr] = xv.y;
        sA[lc + 2][lr] = xv.z;
        sA[lc + 3][lr] = xv.w;

        *(float4*)&sB[wr][wc] = *(const float4*)&W[(k0 + wr) * D + wc];
        __syncthreads();

#pragma unroll
        for (int k = 0; k < GBK; k++) {
            float a[8], b[8];
            *(float4*)&a[0] = *(const float4*)&sA[k][ty * 8];
            *(float4*)&a[4] = *(const float4*)&sA[k][ty * 8 + 4];
            *(float4*)&b[0] = *(const float4*)&sB[k][tx * 8];
            *(float4*)&b[4] = *(const float4*)&sB[k][tx * 8 + 4];
#pragma unroll
            for (int i = 0; i < 8; i++)
#pragma unroll
                for (int j = 0; j < 8; j++)
                    acc[i][j] += a[i] * b[j];
        }
        __syncthreads();
    }

#pragma unroll
    for (int i = 0; i < 8; i++) {
        int gm = block_m + ty * 8 + i;
        if (gm < N_NODES) {
            *(float4*)&g_H[(size_t)gm * D + tx * 8] =
                make_float4(acc[i][0], acc[i][1], acc[i][2], acc[i][3]);
            *(float4*)&g_H[(size_t)gm * D + tx * 8 + 4] =
                make_float4(acc[i][4], acc[i][5], acc[i][6], acc[i][7]);
        }
    }
}

// ---------------------------------------------------------------------------
// CSR build
// ---------------------------------------------------------------------------
__global__ void zero_count_kernel() {
    int i = blockIdx.x * blockDim.x + threadIdx.x;
    if (i < N_NODES) g_count[i] = 0;
}

__global__ void hist_kernel(const int* __restrict__ row) {
    int e = blockIdx.x * blockDim.x + threadIdx.x;
    if (e < N_EDGES) atomicAdd(&g_count[row[e]], 1);
}

// Level 1: per-block sum of 512 counters
__global__ void scan_reduce_kernel() {
    __shared__ int s[SCAN_B];
    int tid = threadIdx.x;
    int i = blockIdx.x * SCAN_B + tid;
    s[tid] = (i < N_NODES) ? g_count[i] : 0;
    __syncthreads();
#pragma unroll
    for (int off = SCAN_B / 2; off > 0; off >>= 1) {
        if (tid < off) s[tid] += s[tid + off];
        __syncthreads();
    }
    if (tid == 0) g_bsum[blockIdx.x] = s[0];
}

// Level 2: exclusive scan of the 98 block sums
__global__ void scan_top_kernel() {
    __shared__ int s[128];
    int tid = threadIdx.x;
    s[tid] = (tid < SCAN_BLOCKS) ? g_bsum[tid] : 0;
    __syncthreads();
#pragma unroll
    for (int off = 1; off < 128; off <<= 1) {
        int t = (tid >= off) ? s[tid - off] : 0;
        __syncthreads();
        s[tid] += t;
        __syncthreads();
    }
    if (tid < SCAN_BLOCKS)
        g_boff[tid] = s[tid] - g_bsum[tid];
    if (tid == 0) g_start[N_NODES] = N_EDGES;
}

// Level 3: intra-block exclusive scan + block offset
__global__ void scan_apply_kernel() {
    __shared__ int s[SCAN_B];
    int tid = threadIdx.x;
    int i = blockIdx.x * SCAN_B + tid;
    int c = (i < N_NODES) ? g_count[i] : 0;
    s[tid] = c;
    __syncthreads();
#pragma unroll
    for (int off = 1; off < SCAN_B; off <<= 1) {
        int t = (tid >= off) ? s[tid - off] : 0;
        __syncthreads();
        s[tid] += t;
        __syncthreads();
    }
    if (i < N_NODES) {
        int ex = g_boff[blockIdx.x] + s[tid] - c;
        g_start[i] = ex;
        g_cursor[i] = ex;
    }
}

// Bucket placement: one packed 8B scattered write per edge
__global__ void permute_kernel(const int* __restrict__ row,
                               const int* __restrict__ col,
                               const float* __restrict__ vals) {
    int e = blockIdx.x * blockDim.x + threadIdx.x;
    if (e >= N_EDGES) return;
    int pos = atomicAdd(&g_cursor[row[e]], 1);
    int2 pk;
    pk.x = __float_as_int(vals[e]);
    pk.y = col[e];
    g_edge[pos] = pk;
}

// ---------------------------------------------------------------------------
// Fused CSR SpMM + bias + ReLU: one warp per output row, register accum.
// ---------------------------------------------------------------------------
__global__ void spmm_kernel(const float* __restrict__ bias,
                            float* __restrict__ out) {
    int warp = (blockIdx.x * blockDim.x + threadIdx.x) >> 5;
    if (warp >= N_NODES) return;
    int lane = threadIdx.x & 31;

    int p   = g_start[warp];
    int end = g_start[warp + 1];

    float4 b = *(const float4*)&bias[lane * 4];
    float4 acc0 = b;
    float4 acc1 = make_float4(0.f, 0.f, 0.f, 0.f);

    for (; p + 1 < end; p += 2) {
        int2 e0 = __ldg(&g_edge[p]);
        int2 e1 = __ldg(&g_edge[p + 1]);
        float v0 = __int_as_float(e0.x);
        float v1 = __int_as_float(e1.x);
        float4 h0 = *(const float4*)&g_H[(size_t)e0.y * D + lane * 4];
        float4 h1 = *(const float4*)&g_H[(size_t)e1.y * D + lane * 4];
        acc0.x += v0 * h0.x; acc0.y += v0 * h0.y;
        acc0.z += v0 * h0.z; acc0.w += v0 * h0.w;
        acc1.x += v1 * h1.x; acc1.y += v1 * h1.y;
        acc1.z += v1 * h1.z; acc1.w += v1 * h1.w;
    }
    if (p < end) {
        int2 e0 = __ldg(&g_edge[p]);
        float v0 = __int_as_float(e0.x);
        float4 h0 = *(const float4*)&g_H[(size_t)e0.y * D + lane * 4];
        acc0.x += v0 * h0.x; acc0.y += v0 * h0.y;
        acc0.z += v0 * h0.z; acc0.w += v0 * h0.w;
    }

    float4 r;
    r.x = fmaxf(acc0.x + acc1.x, 0.f);
    r.y = fmaxf(acc0.y + acc1.y, 0.f);
    r.z = fmaxf(acc0.z + acc1.z, 0.f);
    r.w = fmaxf(acc0.w + acc1.w, 0.f);
    *(float4*)&out[(size_t)warp * D + lane * 4] = r;
}

// ---------------------------------------------------------------------------
// Launch
// ---------------------------------------------------------------------------
extern "C" void kernel_launch(void* const* d_in, const int* in_sizes, int n_in,
                              void* d_out, int out_size) {
    const float* x      = (const float*)d_in[0];   // [50000,128]
    const float* weight = (const float*)d_in[1];   // [128,128]
    const float* bias   = (const float*)d_in[2];   // [128]
    const float* vals   = (const float*)d_in[3];   // [800000]
    const int*   row    = (const int*)d_in[4];     // [800000]
    const int*   col    = (const int*)d_in[5];     // [800000]
    float* out = (float*)d_out;                    // [50000,128]

    // 1) H = X @ W  (register-blocked SGEMM)
    gemm_kernel<<<(N_NODES + GBM - 1) / GBM, 256>>>(x, weight);

    // 2) CSR build (fully parallel 3-level scan + packed bucket placement)
    zero_count_kernel<<<(N_NODES + 255) / 256, 256>>>();
    hist_kernel<<<(N_EDGES + 255) / 256, 256>>>(row);
    scan_reduce_kernel<<<SCAN_BLOCKS, SCAN_B>>>();
    scan_top_kernel<<<1, 128>>>();
    scan_apply_kernel<<<SCAN_BLOCKS, SCAN_B>>>();
    permute_kernel<<<(N_EDGES + 255) / 256, 256>>>(row, col, vals);

    // 3) fused SpMM + bias + ReLU (warp per row)
    spmm_kernel<<<(N_NODES + 7) / 8, 256>>>(bias, out);
}

// round 6
// speedup vs baseline: 1.8032x; 1.0878x over previous
#include <cuda_runtime.h>
#include <cuda_fp16.h>

#define N_NODES 50000
#define N_EDGES 800000
#define D 128

#define SCAN_B 512
#define SCAN_BLOCKS ((N_NODES + SCAN_B - 1) / SCAN_B)   // 98

// Scratch (static __device__ per allocation rules)
__device__ __half g_H[N_NODES * D];       // h = x @ W in fp16  (12.8 MB)
__device__ int    g_count[N_NODES];
__device__ int    g_start[N_NODES + 1];
__device__ int    g_cursor[N_NODES];
__device__ int    g_bsum[SCAN_BLOCKS];
__device__ int    g_boff[SCAN_BLOCKS];
__device__ int2   g_edge[N_EDGES];        // {val_bits, col} sorted by row

// ---------------------------------------------------------------------------
// GEMM: H = X @ W (fp32 compute, fp16 store).
// 128x128 block tile, 8x8 micro-tile per thread, BK=8.
// ---------------------------------------------------------------------------
#define GBM 128
#define GBK 8
#define SA_PAD 4

__global__ void gemm_kernel(const float* __restrict__ X,
                            const float* __restrict__ W) {
    __shared__ float sA[GBK][GBM + SA_PAD];   // X^T tile: sA[k][m]
    __shared__ float sB[GBK][D];              // W tile:   sB[k][n]

    const int tid = threadIdx.x;      // 0..255
    const int tx = tid & 15;          // n: cols tx*8 .. tx*8+7
    const int ty = tid >> 4;          // m: rows ty*8 .. ty*8+7
    const int block_m = blockIdx.x * GBM;

    const int lr = tid >> 1;          // A row within tile 0..127
    const int lc = (tid & 1) * 4;     // A k offset 0 or 4
    const int wr = tid >> 5;          // B k row 0..7
    const int wc = (tid & 31) * 4;    // B n col

    float acc[8][8];
#pragma unroll
    for (int i = 0; i < 8; i++)
#pragma unroll
        for (int j = 0; j < 8; j++) acc[i][j] = 0.f;

    for (int k0 = 0; k0 < D; k0 += GBK) {
        int gm = block_m + lr;
        float4 xv = make_float4(0.f, 0.f, 0.f, 0.f);
        if (gm < N_NODES) xv = *(const float4*)&X[gm * D + k0 + lc];
        sA[lc + 0][lr] = xv.x;
        sA[lc + 1][lr] = xv.y;
        sA[lc + 2][lr] = xv.z;
        sA[lc + 3][lr] = xv.w;

        *(float4*)&sB[wr][wc] = *(const float4*)&W[(k0 + wr) * D + wc];
        __syncthreads();

#pragma unroll
        for (int k = 0; k < GBK; k++) {
            float a[8], b[8];
            *(float4*)&a[0] = *(const float4*)&sA[k][ty * 8];
            *(float4*)&a[4] = *(const float4*)&sA[k][ty * 8 + 4];
            *(float4*)&b[0] = *(const float4*)&sB[k][tx * 8];
            *(float4*)&b[4] = *(const float4*)&sB[k][tx * 8 + 4];
#pragma unroll
            for (int i = 0; i < 8; i++)
#pragma unroll
                for (int j = 0; j < 8; j++)
                    acc[i][j] += a[i] * b[j];
        }
        __syncthreads();
    }

#pragma unroll
    for (int i = 0; i < 8; i++) {
        int gm = block_m + ty * 8 + i;
        if (gm < N_NODES) {
            __half2 h01 = __floats2half2_rn(acc[i][0], acc[i][1]);
            __half2 h23 = __floats2half2_rn(acc[i][2], acc[i][3]);
            __half2 h45 = __floats2half2_rn(acc[i][4], acc[i][5]);
            __half2 h67 = __floats2half2_rn(acc[i][6], acc[i][7]);
            uint4 pk;
            pk.x = *(unsigned*)&h01;
            pk.y = *(unsigned*)&h23;
            pk.z = *(unsigned*)&h45;
            pk.w = *(unsigned*)&h67;
            *(uint4*)&g_H[(size_t)gm * D + tx * 8] = pk;   // 16B = 8 halves
        }
    }
}

// ---------------------------------------------------------------------------
// CSR build
// ---------------------------------------------------------------------------
__global__ void zero_count_kernel() {
    int i = blockIdx.x * blockDim.x + threadIdx.x;
    if (i < N_NODES) g_count[i] = 0;
}

__global__ void hist_kernel(const int* __restrict__ row) {
    int e = blockIdx.x * blockDim.x + threadIdx.x;
    if (e < N_EDGES) atomicAdd(&g_count[row[e]], 1);
}

__global__ void scan_reduce_kernel() {
    __shared__ int s[SCAN_B];
    int tid = threadIdx.x;
    int i = blockIdx.x * SCAN_B + tid;
    s[tid] = (i < N_NODES) ? g_count[i] : 0;
    __syncthreads();
#pragma unroll
    for (int off = SCAN_B / 2; off > 0; off >>= 1) {
        if (tid < off) s[tid] += s[tid + off];
        __syncthreads();
    }
    if (tid == 0) g_bsum[blockIdx.x] = s[0];
}

__global__ void scan_top_kernel() {
    __shared__ int s[128];
    int tid = threadIdx.x;
    s[tid] = (tid < SCAN_BLOCKS) ? g_bsum[tid] : 0;
    __syncthreads();
#pragma unroll
    for (int off = 1; off < 128; off <<= 1) {
        int t = (tid >= off) ? s[tid - off] : 0;
        __syncthreads();
        s[tid] += t;
        __syncthreads();
    }
    if (tid < SCAN_BLOCKS)
        g_boff[tid] = s[tid] - g_bsum[tid];
    if (tid == 0) g_start[N_NODES] = N_EDGES;
}

__global__ void scan_apply_kernel() {
    __shared__ int s[SCAN_B];
    int tid = threadIdx.x;
    int i = blockIdx.x * SCAN_B + tid;
    int c = (i < N_NODES) ? g_count[i] : 0;
    s[tid] = c;
    __syncthreads();
#pragma unroll
    for (int off = 1; off < SCAN_B; off <<= 1) {
        int t = (tid >= off) ? s[tid - off] : 0;
        __syncthreads();
        s[tid] += t;
        __syncthreads();
    }
    if (i < N_NODES) {
        int ex = g_boff[blockIdx.x] + s[tid] - c;
        g_start[i] = ex;
        g_cursor[i] = ex;
    }
}

__global__ void permute_kernel(const int* __restrict__ row,
                               const int* __restrict__ col,
                               const float* __restrict__ vals) {
    int e = blockIdx.x * blockDim.x + threadIdx.x;
    if (e >= N_EDGES) return;
    int pos = atomicAdd(&g_cursor[row[e]], 1);
    int2 pk;
    pk.x = __float_as_int(vals[e]);
    pk.y = col[e];
    g_edge[pos] = pk;
}

// ---------------------------------------------------------------------------
// Fused CSR SpMM + bias + ReLU: one warp per output row.
// Lane gathers 8B (4 fp16) per edge, fp32 accumulate.
// ---------------------------------------------------------------------------
__global__ void spmm_kernel(const float* __restrict__ bias,
                            float* __restrict__ out) {
    int warp = (blockIdx.x * blockDim.x + threadIdx.x) >> 5;
    if (warp >= N_NODES) return;
    int lane = threadIdx.x & 31;

    int p   = g_start[warp];
    int end = g_start[warp + 1];

    float4 b = *(const float4*)&bias[lane * 4];
    float4 acc0 = b;
    float4 acc1 = make_float4(0.f, 0.f, 0.f, 0.f);

    for (; p + 1 < end; p += 2) {
        int2 e0 = __ldg(&g_edge[p]);
        int2 e1 = __ldg(&g_edge[p + 1]);
        float v0 = __int_as_float(e0.x);
        float v1 = __int_as_float(e1.x);
        uint2 u0 = __ldg((const uint2*)&g_H[(size_t)e0.y * D + lane * 4]);
        uint2 u1 = __ldg((const uint2*)&g_H[(size_t)e1.y * D + lane * 4]);
        float2 f00 = __half22float2(*(__half2*)&u0.x);
        float2 f01 = __half22float2(*(__half2*)&u0.y);
        float2 f10 = __half22float2(*(__half2*)&u1.x);
        float2 f11 = __half22float2(*(__half2*)&u1.y);
        acc0.x += v0 * f00.x; acc0.y += v0 * f00.y;
        acc0.z += v0 * f01.x; acc0.w += v0 * f01.y;
        acc1.x += v1 * f10.x; acc1.y += v1 * f10.y;
        acc1.z += v1 * f11.x; acc1.w += v1 * f11.y;
    }
    if (p < end) {
        int2 e0 = __ldg(&g_edge[p]);
        float v0 = __int_as_float(e0.x);
        uint2 u0 = __ldg((const uint2*)&g_H[(size_t)e0.y * D + lane * 4]);
        float2 f00 = __half22float2(*(__half2*)&u0.x);
        float2 f01 = __half22float2(*(__half2*)&u0.y);
        acc0.x += v0 * f00.x; acc0.y += v0 * f00.y;
        acc0.z += v0 * f01.x; acc0.w += v0 * f01.y;
    }

    float4 r;
    r.x = fmaxf(acc0.x + acc1.x, 0.f);
    r.y = fmaxf(acc0.y + acc1.y, 0.f);
    r.z = fmaxf(acc0.z + acc1.z, 0.f);
    r.w = fmaxf(acc0.w + acc1.w, 0.f);
    *(float4*)&out[(size_t)warp * D + lane * 4] = r;
}

// ---------------------------------------------------------------------------
// Launch
// ---------------------------------------------------------------------------
extern "C" void kernel_launch(void* const* d_in, const int* in_sizes, int n_in,
                              void* d_out, int out_size) {
    const float* x      = (const float*)d_in[0];   // [50000,128]
    const float* weight = (const float*)d_in[1];   // [128,128]
    const float* bias   = (const float*)d_in[2];   // [128]
    const float* vals   = (const float*)d_in[3];   // [800000]
    const int*   row    = (const int*)d_in[4];     // [800000]
    const int*   col    = (const int*)d_in[5];     // [800000]
    float* out = (float*)d_out;                    // [50000,128]

    // 1) H = X @ W  (fp32 compute, fp16 store)
    gemm_kernel<<<(N_NODES + GBM - 1) / GBM, 256>>>(x, weight);

    // 2) CSR build
    zero_count_kernel<<<(N_NODES + 255) / 256, 256>>>();
    hist_kernel<<<(N_EDGES + 255) / 256, 256>>>(row);
    scan_reduce_kernel<<<SCAN_BLOCKS, SCAN_B>>>();
    scan_top_kernel<<<1, 128>>>();
    scan_apply_kernel<<<SCAN_BLOCKS, SCAN_B>>>();
    permute_kernel<<<(N_EDGES + 255) / 256, 256>>>(row, col, vals);

    // 3) fused SpMM + bias + ReLU (warp per row)
    spmm_kernel<<<(N_NODES + 7) / 8, 256>>>(bias, out);
}

// round 7
// speedup vs baseline: 1.9477x; 1.0801x over previous
#include <cuda_runtime.h>
#include <cuda_fp16.h>

#define N_NODES 50000
#define N_EDGES 800000
#define D 128

#define SCAN_B 512
#define SCAN_BLOCKS ((N_NODES + SCAN_B - 1) / SCAN_B)   // 98

#define GBM 128
#define GBK 8
#define SA_PAD 4
#define GEMM_BLOCKS ((N_NODES + GBM - 1) / GBM)          // 391
#define PERM_EPT 4                                        // edges per thread
#define PERM_BLOCKS ((N_EDGES + 256 * PERM_EPT - 1) / (256 * PERM_EPT))  // 782

// Scratch (static __device__ per allocation rules)
__device__ __half g_H[N_NODES * D];       // h = x @ W in fp16  (12.8 MB)
__device__ int    g_count[N_NODES];
__device__ int    g_start[N_NODES + 1];
__device__ int    g_cursor[N_NODES];
__device__ int    g_bsum[SCAN_BLOCKS];
__device__ int    g_boff[SCAN_BLOCKS];
__device__ int2   g_edge[N_EDGES];        // {val_bits, col} sorted by row

// ---------------------------------------------------------------------------
// CSR build: counters + histogram + 3-level scan
// ---------------------------------------------------------------------------
__global__ void zero_count_kernel() {
    int i = blockIdx.x * blockDim.x + threadIdx.x;
    if (i < N_NODES) g_count[i] = 0;
}

__global__ void hist_kernel(const int* __restrict__ row) {
    int e = blockIdx.x * blockDim.x + threadIdx.x;
    if (e < N_EDGES) atomicAdd(&g_count[row[e]], 1);
}

__global__ void scan_reduce_kernel() {
    __shared__ int s[SCAN_B];
    int tid = threadIdx.x;
    int i = blockIdx.x * SCAN_B + tid;
    s[tid] = (i < N_NODES) ? g_count[i] : 0;
    __syncthreads();
#pragma unroll
    for (int off = SCAN_B / 2; off > 0; off >>= 1) {
        if (tid < off) s[tid] += s[tid + off];
        __syncthreads();
    }
    if (tid == 0) g_bsum[blockIdx.x] = s[0];
}

__global__ void scan_top_kernel() {
    __shared__ int s[128];
    int tid = threadIdx.x;
    s[tid] = (tid < SCAN_BLOCKS) ? g_bsum[tid] : 0;
    __syncthreads();
#pragma unroll
    for (int off = 1; off < 128; off <<= 1) {
        int t = (tid >= off) ? s[tid - off] : 0;
        __syncthreads();
        s[tid] += t;
        __syncthreads();
    }
    if (tid < SCAN_BLOCKS)
        g_boff[tid] = s[tid] - g_bsum[tid];
    if (tid == 0) g_start[N_NODES] = N_EDGES;
}

__global__ void scan_apply_kernel() {
    __shared__ int s[SCAN_B];
    int tid = threadIdx.x;
    int i = blockIdx.x * SCAN_B + tid;
    int c = (i < N_NODES) ? g_count[i] : 0;
    s[tid] = c;
    __syncthreads();
#pragma unroll
    for (int off = 1; off < SCAN_B; off <<= 1) {
        int t = (tid >= off) ? s[tid - off] : 0;
        __syncthreads();
        s[tid] += t;
        __syncthreads();
    }
    if (i < N_NODES) {
        int ex = g_boff[blockIdx.x] + s[tid] - c;
        g_start[i] = ex;
        g_cursor[i] = ex;
    }
}

// ---------------------------------------------------------------------------
// FAT kernel: blocks [0, GEMM_BLOCKS) run the GEMM tile;
//             blocks [GEMM_BLOCKS, +PERM_BLOCKS) run the edge permute.
// The two are independent — co-residency hides the permute under the GEMM.
// ---------------------------------------------------------------------------
__global__ void gemm_permute_kernel(const float* __restrict__ X,
                                    const float* __restrict__ W,
                                    const int* __restrict__ row,
                                    const int* __restrict__ col,
                                    const float* __restrict__ vals) {
    __shared__ float sA[GBK][GBM + SA_PAD];   // X^T tile: sA[k][m]
    __shared__ float sB[GBK][D];              // W tile:   sB[k][n]
    const int tid = threadIdx.x;              // 0..255

    if (blockIdx.x < GEMM_BLOCKS) {
        // ---------------- GEMM: H = X @ W (fp32 compute, fp16 store) -------
        const int tx = tid & 15;
        const int ty = tid >> 4;
        const int block_m = blockIdx.x * GBM;

        const int lr = tid >> 1;
        const int lc = (tid & 1) * 4;
        const int wr = tid >> 5;
        const int wc = (tid & 31) * 4;

        float acc[8][8];
#pragma unroll
        for (int i = 0; i < 8; i++)
#pragma unroll
            for (int j = 0; j < 8; j++) acc[i][j] = 0.f;

        for (int k0 = 0; k0 < D; k0 += GBK) {
            int gm = block_m + lr;
            float4 xv = make_float4(0.f, 0.f, 0.f, 0.f);
            if (gm < N_NODES) xv = *(const float4*)&X[gm * D + k0 + lc];
            sA[lc + 0][lr] = xv.x;
            sA[lc + 1][lr] = xv.y;
            sA[lc + 2][lr] = xv.z;
            sA[lc + 3][lr] = xv.w;

            *(float4*)&sB[wr][wc] = *(const float4*)&W[(k0 + wr) * D + wc];
            __syncthreads();

#pragma unroll
            for (int k = 0; k < GBK; k++) {
                float a[8], b[8];
                *(float4*)&a[0] = *(const float4*)&sA[k][ty * 8];
                *(float4*)&a[4] = *(const float4*)&sA[k][ty * 8 + 4];
                *(float4*)&b[0] = *(const float4*)&sB[k][tx * 8];
                *(float4*)&b[4] = *(const float4*)&sB[k][tx * 8 + 4];
#pragma unroll
                for (int i = 0; i < 8; i++)
#pragma unroll
                    for (int j = 0; j < 8; j++)
                        acc[i][j] += a[i] * b[j];
            }
            __syncthreads();
        }

#pragma unroll
        for (int i = 0; i < 8; i++) {
            int gm = block_m + ty * 8 + i;
            if (gm < N_NODES) {
                __half2 h01 = __floats2half2_rn(acc[i][0], acc[i][1]);
                __half2 h23 = __floats2half2_rn(acc[i][2], acc[i][3]);
                __half2 h45 = __floats2half2_rn(acc[i][4], acc[i][5]);
                __half2 h67 = __floats2half2_rn(acc[i][6], acc[i][7]);
                uint4 pk;
                pk.x = *(unsigned*)&h01;
                pk.y = *(unsigned*)&h23;
                pk.z = *(unsigned*)&h45;
                pk.w = *(unsigned*)&h67;
                *(uint4*)&g_H[(size_t)gm * D + tx * 8] = pk;
            }
        }
    } else {
        // ---------------- Permute: bucket-place edges sorted by row --------
        int b = blockIdx.x - GEMM_BLOCKS;
        int base = b * (256 * PERM_EPT) + tid;
#pragma unroll
        for (int it = 0; it < PERM_EPT; it++) {
            int e = base + it * 256;
            if (e < N_EDGES) {
                int r = row[e];
                int2 pk;
                pk.x = __float_as_int(vals[e]);
                pk.y = col[e];
                int pos = atomicAdd(&g_cursor[r], 1);
                g_edge[pos] = pk;
            }
        }
    }
}

// ---------------------------------------------------------------------------
// Fused CSR SpMM + bias + ReLU: one warp per output row, unroll-4 (MLP=4).
// ---------------------------------------------------------------------------
__global__ void spmm_kernel(const float* __restrict__ bias,
                            float* __restrict__ out) {
    int warp = (blockIdx.x * blockDim.x + threadIdx.x) >> 5;
    if (warp >= N_NODES) return;
    int lane = threadIdx.x & 31;

    int p   = g_start[warp];
    int end = g_start[warp + 1];

    float4 b = *(const float4*)&bias[lane * 4];
    float4 acc0 = b;
    float4 acc1 = make_float4(0.f, 0.f, 0.f, 0.f);

    for (; p + 4 <= end; p += 4) {
        int2 e0 = __ldg(&g_edge[p]);
        int2 e1 = __ldg(&g_edge[p + 1]);
        int2 e2 = __ldg(&g_edge[p + 2]);
        int2 e3 = __ldg(&g_edge[p + 3]);
        uint2 u0 = __ldg((const uint2*)&g_H[(size_t)e0.y * D + lane * 4]);
        uint2 u1 = __ldg((const uint2*)&g_H[(size_t)e1.y * D + lane * 4]);
        uint2 u2 = __ldg((const uint2*)&g_H[(size_t)e2.y * D + lane * 4]);
        uint2 u3 = __ldg((const uint2*)&g_H[(size_t)e3.y * D + lane * 4]);
        float v0 = __int_as_float(e0.x);
        float v1 = __int_as_float(e1.x);
        float v2 = __int_as_float(e2.x);
        float v3 = __int_as_float(e3.x);

        float2 a0 = __half22float2(*(__half2*)&u0.x);
        float2 b0 = __half22float2(*(__half2*)&u0.y);
        acc0.x += v0 * a0.x; acc0.y += v0 * a0.y;
        acc0.z += v0 * b0.x; acc0.w += v0 * b0.y;

        float2 a1 = __half22float2(*(__half2*)&u1.x);
        float2 b1 = __half22float2(*(__half2*)&u1.y);
        acc1.x += v1 * a1.x; acc1.y += v1 * a1.y;
        acc1.z += v1 * b1.x; acc1.w += v1 * b1.y;

        float2 a2 = __half22float2(*(__half2*)&u2.x);
        float2 b2 = __half22float2(*(__half2*)&u2.y);
        acc0.x += v2 * a2.x; acc0.y += v2 * a2.y;
        acc0.z += v2 * b2.x; acc0.w += v2 * b2.y;

        float2 a3 = __half22float2(*(__half2*)&u3.x);
        float2 b3 = __half22float2(*(__half2*)&u3.y);
        acc1.x += v3 * a3.x; acc1.y += v3 * a3.y;
        acc1.z += v3 * b3.x; acc1.w += v3 * b3.y;
    }
    for (; p < end; p++) {
        int2 e0 = __ldg(&g_edge[p]);
        float v0 = __int_as_float(e0.x);
        uint2 u0 = __ldg((const uint2*)&g_H[(size_t)e0.y * D + lane * 4]);
        float2 a0 = __half22float2(*(__half2*)&u0.x);
        float2 b0 = __half22float2(*(__half2*)&u0.y);
        acc0.x += v0 * a0.x; acc0.y += v0 * a0.y;
        acc0.z += v0 * b0.x; acc0.w += v0 * b0.y;
    }

    float4 r;
    r.x = fmaxf(acc0.x + acc1.x, 0.f);
    r.y = fmaxf(acc0.y + acc1.y, 0.f);
    r.z = fmaxf(acc0.z + acc1.z, 0.f);
    r.w = fmaxf(acc0.w + acc1.w, 0.f);
    *(float4*)&out[(size_t)warp * D + lane * 4] = r;
}

// ---------------------------------------------------------------------------
// Launch
// ---------------------------------------------------------------------------
extern "C" void kernel_launch(void* const* d_in, const int* in_sizes, int n_in,
                              void* d_out, int out_size) {
    const float* x      = (const float*)d_in[0];   // [50000,128]
    const float* weight = (const float*)d_in[1];   // [128,128]
    const float* bias   = (const float*)d_in[2];   // [128]
    const float* vals   = (const float*)d_in[3];   // [800000]
    const int*   row    = (const int*)d_in[4];     // [800000]
    const int*   col    = (const int*)d_in[5];     // [800000]
    float* out = (float*)d_out;                    // [50000,128]

    // 1) CSR offsets
    zero_count_kernel<<<(N_NODES + 255) / 256, 256>>>();
    hist_kernel<<<(N_EDGES + 255) / 256, 256>>>(row);
    scan_reduce_kernel<<<SCAN_BLOCKS, SCAN_B>>>();
    scan_top_kernel<<<1, 128>>>();
    scan_apply_kernel<<<SCAN_BLOCKS, SCAN_B>>>();

    // 2) GEMM and edge-permute co-scheduled in one launch
    gemm_permute_kernel<<<GEMM_BLOCKS + PERM_BLOCKS, 256>>>(x, weight,
                                                            row, col, vals);

    // 3) fused SpMM + bias + ReLU (warp per row)
    spmm_kernel<<<(N_NODES + 7) / 8, 256>>>(bias, out);
}

// round 8
// speedup vs baseline: 2.0309x; 1.0427x over previous
#include <cuda_runtime.h>
#include <cuda_fp16.h>

#define N_NODES 50000
#define N_EDGES 800000
#define D 128

#define SCAN_B 512
#define SCAN_BLOCKS ((N_NODES + SCAN_B - 1) / SCAN_B)   // 98

#define GBM 128
#define GBK 8
#define SA_PAD 4
#define GEMM_BLOCKS ((N_NODES + GBM - 1) / GBM)          // 391
#define PERM_EPT 4
#define PERM_BLOCKS ((N_EDGES + 256 * PERM_EPT - 1) / (256 * PERM_EPT))  // 782

// Scratch (static __device__ per allocation rules; zero-initialized at load)
__device__ __half g_H[N_NODES * D];       // h = x @ W in fp16  (12.8 MB)
__device__ int    g_count[N_NODES];       // self-cleaned each invocation
__device__ int    g_start[N_NODES + 1];
__device__ int    g_cursor[N_NODES];
__device__ int    g_bsum[SCAN_BLOCKS];
__device__ int2   g_edge[N_EDGES];        // {val_bits, col} sorted by row

// ---------------------------------------------------------------------------
// Histogram of row indices (int4-vectorized, 4 edges per thread)
// ---------------------------------------------------------------------------
__global__ void hist_kernel(const int* __restrict__ row) {
    int t = blockIdx.x * blockDim.x + threadIdx.x;
    if (t * 4 >= N_EDGES) return;
    int4 r = __ldg((const int4*)&row[t * 4]);
    atomicAdd(&g_count[r.x], 1);
    atomicAdd(&g_count[r.y], 1);
    atomicAdd(&g_count[r.z], 1);
    atomicAdd(&g_count[r.w], 1);
}

// ---------------------------------------------------------------------------
// Level 1: per-block sum of 512 counters
// ---------------------------------------------------------------------------
__global__ void scan_reduce_kernel() {
    __shared__ int s[SCAN_B];
    int tid = threadIdx.x;
    int i = blockIdx.x * SCAN_B + tid;
    s[tid] = (i < N_NODES) ? g_count[i] : 0;
    __syncthreads();
#pragma unroll
    for (int off = SCAN_B / 2; off > 0; off >>= 1) {
        if (tid < off) s[tid] += s[tid + off];
        __syncthreads();
    }
    if (tid == 0) g_bsum[blockIdx.x] = s[0];
}

// ---------------------------------------------------------------------------
// Level 2+3 fused: every block scans the 98 block-sums in smem (cheap),
// then does its intra-block exclusive scan. Also self-cleans g_count.
// ---------------------------------------------------------------------------
__global__ void scan_apply_kernel() {
    __shared__ int s[SCAN_B];
    __shared__ int sb[128];
    int tid = threadIdx.x;

    if (tid < 128) sb[tid] = (tid < SCAN_BLOCKS) ? g_bsum[tid] : 0;
    __syncthreads();
#pragma unroll
    for (int off = 1; off < 128; off <<= 1) {
        int t = (tid < 128 && tid >= off) ? sb[tid - off] : 0;
        __syncthreads();
        if (tid < 128) sb[tid] += t;    // inclusive scan of block sums
        __syncthreads();
    }
    int boff = (blockIdx.x == 0) ? 0 : sb[blockIdx.x - 1];

    int i = blockIdx.x * SCAN_B + tid;
    int c = (i < N_NODES) ? g_count[i] : 0;
    s[tid] = c;
    __syncthreads();
#pragma unroll
    for (int off = 1; off < SCAN_B; off <<= 1) {
        int t = (tid >= off) ? s[tid - off] : 0;
        __syncthreads();
        s[tid] += t;
        __syncthreads();
    }
    if (i < N_NODES) {
        int ex = boff + s[tid] - c;
        g_start[i] = ex;
        g_cursor[i] = ex;
        g_count[i] = 0;                 // self-clean for next invocation
    }
    if (blockIdx.x == 0 && tid == 0) g_start[N_NODES] = N_EDGES;
}

// ---------------------------------------------------------------------------
// FAT kernel: blocks [0, GEMM_BLOCKS) run the GEMM tile;
//             blocks [GEMM_BLOCKS, +PERM_BLOCKS) run the edge permute.
// ---------------------------------------------------------------------------
__global__ void gemm_permute_kernel(const float* __restrict__ X,
                                    const float* __restrict__ W,
                                    const int* __restrict__ row,
                                    const int* __restrict__ col,
                                    const float* __restrict__ vals) {
    __shared__ float sA[GBK][GBM + SA_PAD];
    __shared__ float sB[GBK][D];
    const int tid = threadIdx.x;

    if (blockIdx.x < GEMM_BLOCKS) {
        const int tx = tid & 15;
        const int ty = tid >> 4;
        const int block_m = blockIdx.x * GBM;
        const int lr = tid >> 1;
        const int lc = (tid & 1) * 4;
        const int wr = tid >> 5;
        const int wc = (tid & 31) * 4;

        float acc[8][8];
#pragma unroll
        for (int i = 0; i < 8; i++)
#pragma unroll
            for (int j = 0; j < 8; j++) acc[i][j] = 0.f;

        for (int k0 = 0; k0 < D; k0 += GBK) {
            int gm = block_m + lr;
            float4 xv = make_float4(0.f, 0.f, 0.f, 0.f);
            if (gm < N_NODES) xv = *(const float4*)&X[gm * D + k0 + lc];
            sA[lc + 0][lr] = xv.x;
            sA[lc + 1][lr] = xv.y;
            sA[lc + 2][lr] = xv.z;
            sA[lc + 3][lr] = xv.w;

            *(float4*)&sB[wr][wc] = *(const float4*)&W[(k0 + wr) * D + wc];
            __syncthreads();

#pragma unroll
            for (int k = 0; k < GBK; k++) {
                float a[8], b[8];
                *(float4*)&a[0] = *(const float4*)&sA[k][ty * 8];
                *(float4*)&a[4] = *(const float4*)&sA[k][ty * 8 + 4];
                *(float4*)&b[0] = *(const float4*)&sB[k][tx * 8];
                *(float4*)&b[4] = *(const float4*)&sB[k][tx * 8 + 4];
#pragma unroll
                for (int i = 0; i < 8; i++)
#pragma unroll
                    for (int j = 0; j < 8; j++)
                        acc[i][j] += a[i] * b[j];
            }
            __syncthreads();
        }

#pragma unroll
        for (int i = 0; i < 8; i++) {
            int gm = block_m + ty * 8 + i;
            if (gm < N_NODES) {
                __half2 h01 = __floats2half2_rn(acc[i][0], acc[i][1]);
                __half2 h23 = __floats2half2_rn(acc[i][2], acc[i][3]);
                __half2 h45 = __floats2half2_rn(acc[i][4], acc[i][5]);
                __half2 h67 = __floats2half2_rn(acc[i][6], acc[i][7]);
                uint4 pk;
                pk.x = *(unsigned*)&h01;
                pk.y = *(unsigned*)&h23;
                pk.z = *(unsigned*)&h45;
                pk.w = *(unsigned*)&h67;
                *(uint4*)&g_H[(size_t)gm * D + tx * 8] = pk;
            }
        }
    } else {
        int b = blockIdx.x - GEMM_BLOCKS;
        int base = b * (256 * PERM_EPT) + tid;
#pragma unroll
        for (int it = 0; it < PERM_EPT; it++) {
            int e = base + it * 256;
            if (e < N_EDGES) {
                int r = row[e];
                int2 pk;
                pk.x = __float_as_int(vals[e]);
                pk.y = col[e];
                int pos = atomicAdd(&g_cursor[r], 1);
                g_edge[pos] = pk;
            }
        }
    }
}

// ---------------------------------------------------------------------------
// Fused CSR SpMM + bias + ReLU: one warp per output row.
// 16 lanes per edge, uint4 (8 halves) per lane, two edges per step,
// unroll-4 steps -> 8 edges in flight per iteration.
// ---------------------------------------------------------------------------
__global__ void spmm_kernel(const float* __restrict__ bias,
                            float* __restrict__ out) {
    int warp = (blockIdx.x * blockDim.x + threadIdx.x) >> 5;
    if (warp >= N_NODES) return;
    int lane = threadIdx.x & 31;
    int half = lane >> 4;              // which edge of the pair
    int sub  = lane & 15;              // 8-col group within the row

    int p   = g_start[warp];
    int end = g_start[warp + 1];

    float acc[8];
#pragma unroll
    for (int j = 0; j < 8; j++) acc[j] = 0.f;

    for (; p < end; p += 8) {
        int2  e[4];
        uint4 h[4];
        float v[4];
#pragma unroll
        for (int u = 0; u < 4; u++) {
            int idx = p + u * 2 + half;
            int idxc = (idx < end) ? idx : p;       // safe in-range fallback
            e[u] = __ldg(&g_edge[idxc]);
            v[u] = (idx < end) ? __int_as_float(e[u].x) : 0.f;
        }
#pragma unroll
        for (int u = 0; u < 4; u++)
            h[u] = __ldg((const uint4*)&g_H[(size_t)e[u].y * D + sub * 8]);
#pragma unroll
        for (int u = 0; u < 4; u++) {
            float2 f0 = __half22float2(*(__half2*)&h[u].x);
            float2 f1 = __half22float2(*(__half2*)&h[u].y);
            float2 f2 = __half22float2(*(__half2*)&h[u].z);
            float2 f3 = __half22float2(*(__half2*)&h[u].w);
            acc[0] += v[u] * f0.x; acc[1] += v[u] * f0.y;
            acc[2] += v[u] * f1.x; acc[3] += v[u] * f1.y;
            acc[4] += v[u] * f2.x; acc[5] += v[u] * f2.y;
            acc[6] += v[u] * f3.x; acc[7] += v[u] * f3.y;
        }
    }

    // combine the two half-warp partial sums
#pragma unroll
    for (int j = 0; j < 8; j++)
        acc[j] += __shfl_xor_sync(0xffffffffu, acc[j], 16);

    if (half == 0) {
        float4 b0 = *(const float4*)&bias[sub * 8];
        float4 b1 = *(const float4*)&bias[sub * 8 + 4];
        float4 r0, r1;
        r0.x = fmaxf(acc[0] + b0.x, 0.f);
        r0.y = fmaxf(acc[1] + b0.y, 0.f);
        r0.z = fmaxf(acc[2] + b0.z, 0.f);
        r0.w = fmaxf(acc[3] + b0.w, 0.f);
        r1.x = fmaxf(acc[4] + b1.x, 0.f);
        r1.y = fmaxf(acc[5] + b1.y, 0.f);
        r1.z = fmaxf(acc[6] + b1.z, 0.f);
        r1.w = fmaxf(acc[7] + b1.w, 0.f);
        *(float4*)&out[(size_t)warp * D + sub * 8]     = r0;
        *(float4*)&out[(size_t)warp * D + sub * 8 + 4] = r1;
    }
}

// ---------------------------------------------------------------------------
// Launch
// ---------------------------------------------------------------------------
extern "C" void kernel_launch(void* const* d_in, const int* in_sizes, int n_in,
                              void* d_out, int out_size) {
    const float* x      = (const float*)d_in[0];   // [50000,128]
    const float* weight = (const float*)d_in[1];   // [128,128]
    const float* bias   = (const float*)d_in[2];   // [128]
    const float* vals   = (const float*)d_in[3];   // [800000]
    const int*   row    = (const int*)d_in[4];     // [800000]
    const int*   col    = (const int*)d_in[5];     // [800000]
    float* out = (float*)d_out;                    // [50000,128]

    // 1) CSR offsets (3 launches; g_count is self-cleaned by scan_apply)
    hist_kernel<<<(N_EDGES / 4 + 255) / 256, 256>>>(row);
    scan_reduce_kernel<<<SCAN_BLOCKS, SCAN_B>>>();
    scan_apply_kernel<<<SCAN_BLOCKS, SCAN_B>>>();

    // 2) GEMM and edge-permute co-scheduled in one launch
    gemm_permute_kernel<<<GEMM_BLOCKS + PERM_BLOCKS, 256>>>(x, weight,
                                                            row, col, vals);

    // 3) fused SpMM + bias + ReLU (warp per row, 2 edges per warp-step)
    spmm_kernel<<<(N_NODES + 7) / 8, 256>>>(bias, out);
}